// round 1
// baseline (speedup 1.0000x reference)
#include <cuda_runtime.h>

// Guided filter, fully fused: out = trunc_clamp( box(A)*x + box(b) )
// A = (box(xy)-box(x)box(y)) / (box(xx)-box(x)^2 + eps), b = box(y) - A*box(x)
// box = 3x3 mean with replication padding (applied independently at BOTH stages).

#define W_IMG 1024
#define H_IMG 1024
#define EPSF 1e-6f

// region: 36x36 input halo tile (stride 37 to dodge bank conflicts)
// A/b:    34x34 (output tile + 1 halo) (stride 35)
__global__ __launch_bounds__(256) void gf_kernel(const float* __restrict__ x,
                                                 const float* __restrict__ y,
                                                 float* __restrict__ out)
{
    __shared__ float sx[36 * 37];
    __shared__ float sy[36 * 37];
    __shared__ float sA[34 * 35];
    __shared__ float sB[34 * 35];

    const int plane = blockIdx.z;                       // 0..23 (N*C)
    const long base = (long)plane * (W_IMG * H_IMG);
    const int ox = blockIdx.x * 32;
    const int oy = blockIdx.y * 32;
    const int tid = threadIdx.x;
    const float inv9 = 1.0f / 9.0f;

    // ---- Phase 0: load 36x36 halo tile of x and y (replication via clamp) ----
    for (int idx = tid; idx < 36 * 36; idx += 256) {
        int r = idx / 36, c = idx - r * 36;
        int gy = min(max(oy + r - 2, 0), H_IMG - 1);
        int gx = min(max(ox + c - 2, 0), W_IMG - 1);
        long g = base + (long)gy * W_IMG + gx;
        sx[r * 37 + c] = x[g];
        sy[r * 37 + c] = y[g];
    }
    __syncthreads();

    // ---- Phase 1: A,b on 34x34 (output + halo 1) ----
    // A-coordinate itself is clamped to the image (replication pad of A at
    // stage 2), and the x/y coords of its 3x3 window are clamped again
    // (replication pad at stage 1).
    for (int idx = tid; idx < 34 * 34; idx += 256) {
        int ar = idx / 34, ac = idx - ar * 34;
        int gy0 = min(max(oy + ar - 1, 0), H_IMG - 1);  // clamped A row
        int gx0 = min(max(ox + ac - 1, 0), W_IMG - 1);  // clamped A col
        int ry[3], rx[3];
        #pragma unroll
        for (int d = 0; d < 3; d++) {
            ry[d] = min(max(gy0 + d - 1, 0), H_IMG - 1) - oy + 2;
            rx[d] = min(max(gx0 + d - 1, 0), W_IMG - 1) - ox + 2;
        }
        float sxs = 0.f, sys = 0.f, sxy = 0.f, sxx = 0.f;
        #pragma unroll
        for (int i = 0; i < 3; i++) {
            #pragma unroll
            for (int j = 0; j < 3; j++) {
                float xv = sx[ry[i] * 37 + rx[j]];
                float yv = sy[ry[i] * 37 + rx[j]];
                sxs += xv;
                sys += yv;
                sxy = fmaf(xv, yv, sxy);
                sxx = fmaf(xv, xv, sxx);
            }
        }
        float mx  = sxs * inv9;
        float my  = sys * inv9;
        float cov = fmaf(sxy, inv9, -mx * my);
        float var = fmaf(sxx, inv9, -mx * mx);
        float A   = cov / (var + EPSF);
        float b   = fmaf(-A, mx, my);
        sA[ar * 35 + ac] = A;
        sB[ar * 35 + ac] = b;
    }
    __syncthreads();

    // ---- Phase 2: box(A), box(b) (replication pad of A/b), combine, store ----
    for (int idx = tid; idx < 32 * 32; idx += 256) {
        int r = idx >> 5, c = idx & 31;
        int gy = oy + r, gx = ox + c;
        int ay[3], axi[3];
        #pragma unroll
        for (int d = 0; d < 3; d++) {
            ay[d]  = min(max(gy + d - 1, 0), H_IMG - 1) - oy + 1;
            axi[d] = min(max(gx + d - 1, 0), W_IMG - 1) - ox + 1;
        }
        float sa = 0.f, sb = 0.f;
        #pragma unroll
        for (int i = 0; i < 3; i++) {
            #pragma unroll
            for (int j = 0; j < 3; j++) {
                sa += sA[ay[i] * 35 + axi[j]];
                sb += sB[ay[i] * 35 + axi[j]];
            }
        }
        float xc  = sx[(r + 2) * 37 + (c + 2)];
        float res = fmaf(sa * inv9, xc, sb * inv9);
        res = truncf(res);                       // toward zero, like torch .int()
        res = fminf(fmaxf(res, 0.0f), 255.0f);   // clamp(0,255)
        out[base + (long)gy * W_IMG + gx] = res;
    }
}

extern "C" void kernel_launch(void* const* d_in, const int* in_sizes, int n_in,
                              void* d_out, int out_size) {
    const float* x = (const float*)d_in[0];
    const float* y = (const float*)d_in[1];
    float* out     = (float*)d_out;

    // 8*3 = 24 planes of 1024x1024, 32x32 output tiles
    dim3 grid(W_IMG / 32, H_IMG / 32, 24);
    gf_kernel<<<grid, 256>>>(x, y, out);
}

// round 2
// speedup vs baseline: 2.5769x; 2.5769x over previous
#include <cuda_runtime.h>

// Guided filter, fully fused, SMEM-free warp-sliding implementation.
//
// One warp owns a 32-lane column band (28 useful output columns, 2-lane halo
// on each side) and slides down CHUNK_H image rows. Horizontal 3-tap box sums
// come from warp shuffles; vertical 3-tap sums from 3-deep register rings.
// Replication padding: stage 1 via clamped load columns/rows (duplicated lane
// values make shuffles return the padded value); stage 2 (box over A,b) via
// predicated selects at image columns 0/1023 and ring copies at rows 0/1023.

#define W 1024
#define H 1024
#define EPSF 1e-6f
#define C9 (1.0f / 9.0f)

#define OUT_COLS_PER_WARP 28
#define BANDS 37            // ceil(1024 / 28)
#define CHUNK_H 128
#define CHUNKS (H / CHUNK_H) // 8
#define WARPS_PER_BLOCK 8
#define UNITS (24 * BANDS * CHUNKS)                 // 7104 warps
#define NBLOCKS (UNITS / WARPS_PER_BLOCK)           // 888

__device__ __forceinline__ float hsum3(float v) {
    float l = __shfl_up_sync(0xffffffffu, v, 1);    // lane0 keeps own (halo lane, unused)
    float r = __shfl_down_sync(0xffffffffu, v, 1);  // lane31 keeps own
    return l + v + r;
}

__global__ __launch_bounds__(256) void gf_kernel(const float* __restrict__ x,
                                                 const float* __restrict__ y,
                                                 float* __restrict__ out)
{
    const int wid  = threadIdx.x >> 5;
    const int lane = threadIdx.x & 31;
    const int g    = blockIdx.x * WARPS_PER_BLOCK + wid;

    const int plane = g / (BANDS * CHUNKS);
    const int rem   = g - plane * (BANDS * CHUNKS);
    const int band  = rem / CHUNKS;
    const int chunk = rem - band * CHUNKS;

    const int cbase = band * OUT_COLS_PER_WARP - 2;
    const int icr   = cbase + lane;                  // raw column of this lane
    const int ic    = min(max(icr, 0), W - 1);       // clamped load column
    const int r0    = chunk * CHUNK_H;

    const bool pl = (icr == 0);          // stage-2 left replication
    const bool pr = (icr == W - 1);      // stage-2 right replication
    const bool do_store = (lane >= 2) && (lane <= 29) && (icr >= 0) && (icr < W);

    const size_t pb = (size_t)plane * (W * H);
    const float* __restrict__ px = x + pb + ic;
    const float* __restrict__ py = y + pb + ic;
    float* po = out + pb + (size_t)r0 * W + ic;      // ic == icr wherever stored

    // register rings (slots rotate via the unrolled STEP macro, never indexed
    // dynamically)
    float hx[3], hy[3], hxy[3], hxx[3];   // horizontal sums of x, y, x*y, x*x
    float hA[3], hB[3];                   // horizontal sums of A, b
    float xc[3];                          // center x values

    // ---------------- prologue: fill rings for rows r0-2 .. r0+1 ----------------
    {
        float txx0, txy0, tx0, ty0, txx1, txy1, tx1, ty1;
        // row r0-2 (clamped at top)
        {
            int rc = max(r0 - 2, 0);
            float xv = px[(size_t)rc * W], yv = py[(size_t)rc * W];
            tx0 = hsum3(xv); ty0 = hsum3(yv);
            txy0 = hsum3(xv * yv); txx0 = hsum3(xv * xv);
        }
        // row r0-1
        {
            int rc = max(r0 - 1, 0);
            float xv = px[(size_t)rc * W], yv = py[(size_t)rc * W];
            tx1 = hsum3(xv); ty1 = hsum3(yv);
            txy1 = hsum3(xv * yv); txx1 = hsum3(xv * xv);
        }
        // row r0 -> slot 0
        {
            float xv = px[(size_t)r0 * W], yv = py[(size_t)r0 * W];
            hx[0] = hsum3(xv); hy[0] = hsum3(yv);
            hxy[0] = hsum3(xv * yv); hxx[0] = hsum3(xv * xv);
            xc[0] = xv;
        }
        // row r0+1 -> slot 1
        {
            float xv = px[(size_t)(r0 + 1) * W], yv = py[(size_t)(r0 + 1) * W];
            hx[1] = hsum3(xv); hy[1] = hsum3(yv);
            hxy[1] = hsum3(xv * yv); hxx[1] = hsum3(xv * xv);
            xc[1] = xv;
        }

        // A,b at row r0-1  (h rows r0-2, r0-1, r0)
        {
            float Sx = tx0 + tx1 + hx[0], Sy = ty0 + ty1 + hy[0];
            float Sxy = txy0 + txy1 + hxy[0], Sxx = txx0 + txx1 + hxx[0];
            float mx = Sx * C9, my = Sy * C9;
            float cov = fmaf(Sxy, C9, -(mx * my));
            float var = fmaf(Sxx, C9, fmaf(-mx, mx, EPSF));
            float Av = __fdividef(cov, var);
            float Bv = fmaf(-Av, mx, my);
            float Al = __shfl_up_sync(0xffffffffu, Av, 1);
            float Ar = __shfl_down_sync(0xffffffffu, Av, 1);
            float Bl = __shfl_up_sync(0xffffffffu, Bv, 1);
            float Br = __shfl_down_sync(0xffffffffu, Bv, 1);
            Al = pl ? Av : Al;  Bl = pl ? Bv : Bl;
            Ar = pr ? Av : Ar;  Br = pr ? Bv : Br;
            hA[0] = Al + Av + Ar;  hB[0] = Bl + Bv + Br;
        }
        // A,b at row r0  (h rows r0-1, r0, r0+1)
        {
            float Sx = tx1 + hx[0] + hx[1], Sy = ty1 + hy[0] + hy[1];
            float Sxy = txy1 + hxy[0] + hxy[1], Sxx = txx1 + hxx[0] + hxx[1];
            float mx = Sx * C9, my = Sy * C9;
            float cov = fmaf(Sxy, C9, -(mx * my));
            float var = fmaf(Sxx, C9, fmaf(-mx, mx, EPSF));
            float Av = __fdividef(cov, var);
            float Bv = fmaf(-Av, mx, my);
            float Al = __shfl_up_sync(0xffffffffu, Av, 1);
            float Ar = __shfl_down_sync(0xffffffffu, Av, 1);
            float Bl = __shfl_up_sync(0xffffffffu, Bv, 1);
            float Br = __shfl_down_sync(0xffffffffu, Bv, 1);
            Al = pl ? Av : Al;  Bl = pl ? Bv : Bl;
            Ar = pr ? Av : Ar;  Br = pr ? Bv : Br;
            hA[1] = Al + Av + Ar;  hB[1] = Bl + Bv + Br;
        }
        if (r0 == 0) {           // top replication: A row -1 := A row 0
            hA[0] = hA[1];
            hB[0] = hB[1];
        }
    }

    // pointers for the sliding loads (row r0+2 first; r0+2 <= 962 always valid)
    const float* pxr = px + (size_t)(r0 + 2) * W;
    const float* pyr = py + (size_t)(r0 + 2) * W;

    // One STEP produces output row rr = r0+i.
    // Slot ic2 receives: h at row rr+2, hA/hB at row rr+1, xc at row rr+2.
    // Slot ia holds: h row rr, hA row rr-1, xc row rr. Slot ib: rr+1 / rr / rr+1.
#define STEP(ia, ib, ic2, i) { \
        const int rr = r0 + (i); \
        float xv = *pxr, yv = *pyr; \
        if (rr + 2 < H - 1) { pxr += W; pyr += W; } \
        hx[ic2] = hsum3(xv); hy[ic2] = hsum3(yv); \
        hxy[ic2] = hsum3(xv * yv); hxx[ic2] = hsum3(xv * xv); \
        xc[ic2] = xv; \
        float Sx = hx[ia] + hx[ib] + hx[ic2]; \
        float Sy = hy[ia] + hy[ib] + hy[ic2]; \
        float Sxy = hxy[ia] + hxy[ib] + hxy[ic2]; \
        float Sxx = hxx[ia] + hxx[ib] + hxx[ic2]; \
        float mx = Sx * C9, my = Sy * C9; \
        float cov = fmaf(Sxy, C9, -(mx * my)); \
        float var = fmaf(Sxx, C9, fmaf(-mx, mx, EPSF)); \
        float Av = __fdividef(cov, var); \
        float Bv = fmaf(-Av, mx, my); \
        float Al = __shfl_up_sync(0xffffffffu, Av, 1); \
        float Ar = __shfl_down_sync(0xffffffffu, Av, 1); \
        float Bl = __shfl_up_sync(0xffffffffu, Bv, 1); \
        float Br = __shfl_down_sync(0xffffffffu, Bv, 1); \
        Al = pl ? Av : Al;  Bl = pl ? Bv : Bl; \
        Ar = pr ? Av : Ar;  Br = pr ? Bv : Br; \
        float hAn = Al + Av + Ar; \
        float hBn = Bl + Bv + Br; \
        if (rr + 1 >= H) { hAn = hA[ib]; hBn = hB[ib]; } /* bottom replication */ \
        hA[ic2] = hAn;  hB[ic2] = hBn; \
        float SA = hA[ia] + hA[ib] + hAn; \
        float SB = hB[ia] + hB[ib] + hBn; \
        float res = fmaf(SA * C9, xc[ia], SB * C9); \
        res = fminf(fmaxf(truncf(res), 0.0f), 255.0f); \
        if (do_store) *po = res; \
        po += W; \
    }

    // CHUNK_H = 128 rows: 42 triples (rows 0..125) + rows 126, 127
    for (int i = 0; i < CHUNK_H - 2; i += 3) {
        STEP(0, 1, 2, i)
        STEP(1, 2, 0, i + 1)
        STEP(2, 0, 1, i + 2)
    }
    STEP(0, 1, 2, CHUNK_H - 2)   // i = 126, 126 % 3 == 0
    STEP(1, 2, 0, CHUNK_H - 1)   // i = 127
#undef STEP
}

extern "C" void kernel_launch(void* const* d_in, const int* in_sizes, int n_in,
                              void* d_out, int out_size) {
    const float* x = (const float*)d_in[0];
    const float* y = (const float*)d_in[1];
    float* out     = (float*)d_out;

    gf_kernel<<<NBLOCKS, 32 * WARPS_PER_BLOCK>>>(x, y, out);
}